// round 1
// baseline (speedup 1.0000x reference)
#include <cuda_runtime.h>
#include <cstdint>

// -------------------------------------------------------------------------
// Cooccurrence scatter-add:
//   out[l, r] += 1.0  for each pair, on top of the initial `weight` matrix.
// weight: 8192 x 8192 fp32 (256 MB). pairs: 8M int32 each.
// Strategy: (1) vectorized copy weight -> out, (2) REDG atomic scatter.
// -------------------------------------------------------------------------

static constexpr int VOCAB_SHIFT = 13;  // N_VOCAB = 8192

__global__ void copy_weight_kernel(const float4* __restrict__ w,
                                   float4* __restrict__ out,
                                   int n4) {
    int i = blockIdx.x * blockDim.x + threadIdx.x;
    int stride = gridDim.x * blockDim.x;
    #pragma unroll 4
    for (; i < n4; i += stride) {
        out[i] = w[i];
    }
}

__global__ void scatter_add_vec4_kernel(const int4* __restrict__ left,
                                        const int4* __restrict__ right,
                                        float* __restrict__ out,
                                        int n4) {
    int i = blockIdx.x * blockDim.x + threadIdx.x;
    if (i >= n4) return;
    int4 l = left[i];
    int4 r = right[i];
    // offsets fit in 32-bit: max 8191*8192+8191 = 67,108,863 < 2^31
    atomicAdd(out + ((unsigned)l.x << VOCAB_SHIFT) + (unsigned)r.x, 1.0f);
    atomicAdd(out + ((unsigned)l.y << VOCAB_SHIFT) + (unsigned)r.y, 1.0f);
    atomicAdd(out + ((unsigned)l.z << VOCAB_SHIFT) + (unsigned)r.z, 1.0f);
    atomicAdd(out + ((unsigned)l.w << VOCAB_SHIFT) + (unsigned)r.w, 1.0f);
}

__global__ void scatter_add_tail_kernel(const int* __restrict__ left,
                                        const int* __restrict__ right,
                                        float* __restrict__ out,
                                        int start, int n) {
    int i = start + blockIdx.x * blockDim.x + threadIdx.x;
    if (i >= n) return;
    atomicAdd(out + ((unsigned)left[i] << VOCAB_SHIFT) + (unsigned)right[i], 1.0f);
}

extern "C" void kernel_launch(void* const* d_in, const int* in_sizes, int n_in,
                              void* d_out, int out_size) {
    const int*   left   = (const int*)d_in[0];
    const int*   right  = (const int*)d_in[1];
    const float* weight = (const float*)d_in[2];
    float*       out    = (float*)d_out;

    const int n_pairs = in_sizes[0];   // 8,000,000
    const int n_out   = out_size;      // 67,108,864

    // 1) Copy weight -> out (out is poisoned by harness; full write required).
    {
        int n4 = n_out >> 2;  // out_size divisible by 4 (8192*8192)
        int threads = 256;
        int blocks = 2048;    // grid-stride over 16M float4
        copy_weight_kernel<<<blocks, threads>>>(
            (const float4*)weight, (float4*)out, n4);
    }

    // 2) Scatter-add increments.
    {
        int n4 = n_pairs >> 2;
        if (n4 > 0) {
            int threads = 256;
            int blocks = (n4 + threads - 1) / threads;
            scatter_add_vec4_kernel<<<blocks, threads>>>(
                (const int4*)left, (const int4*)right, out, n4);
        }
        int done = n4 << 2;
        int rem = n_pairs - done;
        if (rem > 0) {
            scatter_add_tail_kernel<<<1, 256>>>(left, right, out, done, n_pairs);
        }
    }
}

// round 2
// speedup vs baseline: 1.6360x; 1.6360x over previous
#include <cuda_runtime.h>
#include <cstdint>

// -------------------------------------------------------------------------
// Cooccurrence scatter-add, L2-partitioned:
//   out[l, r] += 1.0 for each (l, r) pair, on top of initial `weight`.
// weight/out: 8192 x 8192 fp32 = 256 MB.  pairs: 8M int32 each.
//
// The matrix doesn't fit L2 (126 MB), so naive random atomics thrash DRAM
// (measured 262us @ 2.75 TB/s). Instead, process 4 row-partitions of
// 2048 rows = 64 MB each:
//   for p in 0..3:  copy slice p (write-allocates slice into L2)
//                   scatter pass over all pairs predicated to slice p
// Atomics then hit L2-resident lines; DRAM sees only streaming traffic.
// -------------------------------------------------------------------------

static constexpr int VOCAB_SHIFT = 13;        // N_VOCAB = 8192
static constexpr int N_PARTS = 4;
static constexpr int ROWS_PER_PART = 8192 / N_PARTS;  // 2048

__global__ void copy_slice_kernel(const float4* __restrict__ w,
                                  float4* __restrict__ out,
                                  int base4, int n4) {
    int i = blockIdx.x * blockDim.x + threadIdx.x;
    int stride = gridDim.x * blockDim.x;
    for (; i < n4; i += stride) {
        out[base4 + i] = w[base4 + i];
    }
}

__global__ void scatter_pass_kernel(const int4* __restrict__ left,
                                    const int4* __restrict__ right,
                                    float* __restrict__ out,
                                    int n4, int row_lo) {
    int i = blockIdx.x * blockDim.x + threadIdx.x;
    if (i >= n4) return;
    int4 l = left[i];
    int4 r = right[i];
    // Predicated atomics: only pairs whose row is in [row_lo, row_lo+2048).
    if ((unsigned)(l.x - row_lo) < (unsigned)ROWS_PER_PART)
        atomicAdd(out + ((unsigned)l.x << VOCAB_SHIFT) + (unsigned)r.x, 1.0f);
    if ((unsigned)(l.y - row_lo) < (unsigned)ROWS_PER_PART)
        atomicAdd(out + ((unsigned)l.y << VOCAB_SHIFT) + (unsigned)r.y, 1.0f);
    if ((unsigned)(l.z - row_lo) < (unsigned)ROWS_PER_PART)
        atomicAdd(out + ((unsigned)l.z << VOCAB_SHIFT) + (unsigned)r.z, 1.0f);
    if ((unsigned)(l.w - row_lo) < (unsigned)ROWS_PER_PART)
        atomicAdd(out + ((unsigned)l.w << VOCAB_SHIFT) + (unsigned)r.w, 1.0f);
}

__global__ void scatter_tail_kernel(const int* __restrict__ left,
                                    const int* __restrict__ right,
                                    float* __restrict__ out,
                                    int start, int n) {
    int i = start + blockIdx.x * blockDim.x + threadIdx.x;
    if (i >= n) return;
    atomicAdd(out + ((unsigned)left[i] << VOCAB_SHIFT) + (unsigned)right[i], 1.0f);
}

extern "C" void kernel_launch(void* const* d_in, const int* in_sizes, int n_in,
                              void* d_out, int out_size) {
    const int*   left   = (const int*)d_in[0];
    const int*   right  = (const int*)d_in[1];
    const float* weight = (const float*)d_in[2];
    float*       out    = (float*)d_out;

    const int n_pairs = in_sizes[0];      // 8,000,000
    const int n_out   = out_size;         // 67,108,864 floats

    const int slice_elems  = n_out / N_PARTS;       // 16,777,216 floats
    const int slice4       = slice_elems >> 2;      // float4 count per slice
    const int n4           = n_pairs >> 2;          // int4 groups
    const int scat_blocks  = (n4 + 255) / 256;

    for (int p = 0; p < N_PARTS; p++) {
        // (a) Copy slice p: pulls the 64 MB slice into L2 via write-allocate.
        copy_slice_kernel<<<2048, 256>>>(
            (const float4*)weight, (float4*)out, p * slice4, slice4);

        // (b) Scatter all pairs whose row lands in slice p (L2-resident).
        if (n4 > 0) {
            scatter_pass_kernel<<<scat_blocks, 256>>>(
                (const int4*)left, (const int4*)right, out,
                n4, p * ROWS_PER_PART);
        }
    }

    // Tail (n_pairs % 4 != 0) — unpartitioned, tiny or empty.
    int done = n4 << 2;
    if (n_pairs - done > 0) {
        scatter_tail_kernel<<<1, 256>>>(left, right, out, done, n_pairs);
    }
}